// round 1
// baseline (speedup 1.0000x reference)
#include <cuda_runtime.h>
#include <cuda_bf16.h>
#include <cstdint>

// Problem constants
#define BB 512
#define TT 128
#define CC 512
#define HH 8
#define LL 6
#define VV 13
#define DD 64
#define MM (BB*TT)          // 65536 rows in the token stream

// ---------------------------------------------------------------------------
// Scratch: 6 buffers of [M, C] fp32 = 6 * 128 MiB (static __device__, no alloc)
// ---------------------------------------------------------------------------
#define BUF_ELEMS ((size_t)MM * CC)
__device__ float g_scratch[6 * BUF_ELEMS];

// ---------------------------------------------------------------------------
// Embedding: x[b,t,:] = wte[tok[b,t],:] + wpe[t,:]
// grid = M blocks, 128 threads, one float4 per thread
// ---------------------------------------------------------------------------
__global__ void embed_kernel(const int* __restrict__ tok,
                             const float* __restrict__ wte,
                             const float* __restrict__ wpe,
                             float* __restrict__ x) {
    int row = blockIdx.x;
    int tid = threadIdx.x;                 // 0..127 (float4 index into 512 floats)
    int tkn = tok[row];
    int t = row & (TT - 1);                // row = b*T + t
    float4 a = ((const float4*)(wte + (size_t)tkn * CC))[tid];
    float4 p = ((const float4*)(wpe + (size_t)t * CC))[tid];
    float4 o;
    o.x = a.x + p.x; o.y = a.y + p.y; o.z = a.z + p.z; o.w = a.w + p.w;
    ((float4*)(x + (size_t)row * CC))[tid] = o;
}

// ---------------------------------------------------------------------------
// SGEMM: out[M,512] = A[M,512] @ W[512,512] + bias (+ residual)
// BM=BN=128, BK=16, 256 threads, 8x8 per thread (4+4 rake layout)
// ---------------------------------------------------------------------------
__global__ __launch_bounds__(256)
void sgemm_kernel(const float* __restrict__ A, const float* __restrict__ W,
                  const float* __restrict__ bias, const float* __restrict__ res,
                  float* __restrict__ out) {
    const int K = CC, N = CC;
    __shared__ float As[16][128];
    __shared__ float Bs[16][128];

    int bx = blockIdx.x;                   // n-block (0..3)
    int by = blockIdx.y;                   // m-block (0..511)
    int tid = threadIdx.x;
    int tx = tid & 15;
    int ty = tid >> 4;

    const float* Ab = A + (size_t)by * 128 * K;
    const float* Wb = W + bx * 128;

    float acc[8][8];
    #pragma unroll
    for (int i = 0; i < 8; i++)
        #pragma unroll
        for (int j = 0; j < 8; j++) acc[i][j] = 0.f;

    for (int k0 = 0; k0 < K; k0 += 16) {
        // A tile: 128 rows x 16 k, stored transposed As[k][row]
        #pragma unroll
        for (int s = 0; s < 2; s++) {
            int slot = tid + s * 256;      // 512 float4 slots
            int row = slot >> 2, kc = slot & 3;
            float4 v = *(const float4*)(Ab + (size_t)row * K + k0 + kc * 4);
            As[kc * 4 + 0][row] = v.x;
            As[kc * 4 + 1][row] = v.y;
            As[kc * 4 + 2][row] = v.z;
            As[kc * 4 + 3][row] = v.w;
        }
        // W tile: 16 k x 128 n
        #pragma unroll
        for (int s = 0; s < 2; s++) {
            int slot = tid + s * 256;
            int k = slot >> 5, n4 = slot & 31;
            *(float4*)(&Bs[k][n4 * 4]) = *(const float4*)(Wb + (size_t)(k0 + k) * N + n4 * 4);
        }
        __syncthreads();

        #pragma unroll
        for (int k = 0; k < 16; k++) {
            float4 a0 = *(const float4*)(&As[k][ty * 4]);
            float4 a1 = *(const float4*)(&As[k][64 + ty * 4]);
            float4 b0 = *(const float4*)(&Bs[k][tx * 4]);
            float4 b1 = *(const float4*)(&Bs[k][64 + tx * 4]);
            float ar[8] = {a0.x, a0.y, a0.z, a0.w, a1.x, a1.y, a1.z, a1.w};
            float br[8] = {b0.x, b0.y, b0.z, b0.w, b1.x, b1.y, b1.z, b1.w};
            #pragma unroll
            for (int i = 0; i < 8; i++)
                #pragma unroll
                for (int j = 0; j < 8; j++)
                    acc[i][j] += ar[i] * br[j];
        }
        __syncthreads();
    }

    // Epilogue: bias (+ residual), float4 stores
    int c0 = bx * 128 + tx * 4;
    int c1 = c0 + 64;
    float4 bias0 = *(const float4*)(bias + c0);
    float4 bias1 = *(const float4*)(bias + c1);
    #pragma unroll
    for (int i = 0; i < 8; i++) {
        int r = by * 128 + ((i < 4) ? (ty * 4 + i) : (64 + ty * 4 + i - 4));
        float4 o0, o1;
        o0.x = acc[i][0] + bias0.x; o0.y = acc[i][1] + bias0.y;
        o0.z = acc[i][2] + bias0.z; o0.w = acc[i][3] + bias0.w;
        o1.x = acc[i][4] + bias1.x; o1.y = acc[i][5] + bias1.y;
        o1.z = acc[i][6] + bias1.z; o1.w = acc[i][7] + bias1.w;
        if (res) {
            float4 r0 = *(const float4*)(res + (size_t)r * N + c0);
            float4 r1 = *(const float4*)(res + (size_t)r * N + c1);
            o0.x += r0.x; o0.y += r0.y; o0.z += r0.z; o0.w += r0.w;
            o1.x += r1.x; o1.y += r1.y; o1.z += r1.z; o1.w += r1.w;
        }
        *(float4*)(out + (size_t)r * N + c0) = o0;
        *(float4*)(out + (size_t)r * N + c1) = o1;
    }
}

// ---------------------------------------------------------------------------
// Per-position head attention: att[h,g] = softmax_g(q[h,:].k[g,:] / sqrt(D))
// hid[h,:] = att[h,:] @ v     (one block of 64 threads per (b,t) position)
// ---------------------------------------------------------------------------
__global__ void attn_kernel(const float* __restrict__ q,
                            const float* __restrict__ k,
                            const float* __restrict__ v,
                            float* __restrict__ out) {
    int r = blockIdx.x;
    int t = threadIdx.x;                    // 0..63
    __shared__ float qs[512], ks[512], vs[512], att_s[64];

    const float4* qp = (const float4*)(q + (size_t)r * CC);
    const float4* kp = (const float4*)(k + (size_t)r * CC);
    const float4* vp = (const float4*)(v + (size_t)r * CC);
    #pragma unroll
    for (int i = t; i < 128; i += 64) {
        ((float4*)qs)[i] = qp[i];
        ((float4*)ks)[i] = kp[i];
        ((float4*)vs)[i] = vp[i];
    }
    __syncthreads();

    int h = t >> 3, g = t & 7;
    float s = 0.f;
    #pragma unroll
    for (int d = 0; d < DD; d++) s += qs[h * DD + d] * ks[g * DD + d];
    s *= 0.125f;                            // 1/sqrt(64)

    // softmax over g (groups of 8, intra-warp)
    float m = s;
    #pragma unroll
    for (int o = 1; o < 8; o <<= 1) m = fmaxf(m, __shfl_xor_sync(0xffffffffu, m, o, 8));
    float e = expf(s - m);
    float sum = e;
    #pragma unroll
    for (int o = 1; o < 8; o <<= 1) sum += __shfl_xor_sync(0xffffffffu, sum, o, 8);
    att_s[t] = e / sum;
    __syncthreads();

    // hid[h][d]: thread (h, j=t&7) computes d = j*8 .. j*8+7
    int j = t & 7;
    float accv[8] = {0.f, 0.f, 0.f, 0.f, 0.f, 0.f, 0.f, 0.f};
    #pragma unroll
    for (int g2 = 0; g2 < 8; g2++) {
        float a = att_s[h * 8 + g2];
        #pragma unroll
        for (int jj = 0; jj < 8; jj++)
            accv[jj] += a * vs[g2 * DD + j * 8 + jj];
    }
    float* op = out + (size_t)r * CC + h * DD + j * 8;
    #pragma unroll
    for (int jj = 0; jj < 8; jj++) op[jj] = accv[jj];
}

// ---------------------------------------------------------------------------
// LayerNorm (warp per row): xo = (y - mean)/sqrt(var + 1e-5) * g + b
// ---------------------------------------------------------------------------
__global__ void ln_kernel(const float* __restrict__ y, const float* __restrict__ g,
                          const float* __restrict__ b, float* __restrict__ xo) {
    int warp = threadIdx.x >> 5;
    int lane = threadIdx.x & 31;
    size_t row = (size_t)blockIdx.x * 8 + warp;

    const float4* yp = (const float4*)(y + row * CC);
    float4 v[4];
    float s = 0.f, s2 = 0.f;
    #pragma unroll
    for (int i = 0; i < 4; i++) {
        v[i] = yp[lane + 32 * i];
        s  += v[i].x + v[i].y + v[i].z + v[i].w;
        s2 += v[i].x * v[i].x + v[i].y * v[i].y + v[i].z * v[i].z + v[i].w * v[i].w;
    }
    #pragma unroll
    for (int o = 16; o; o >>= 1) {
        s  += __shfl_xor_sync(0xffffffffu, s, o);
        s2 += __shfl_xor_sync(0xffffffffu, s2, o);
    }
    float mean = s * (1.f / 512.f);
    float var = s2 * (1.f / 512.f) - mean * mean;
    float rstd = rsqrtf(var + 1e-5f);

    float4* xp = (float4*)(xo + row * CC);
    const float4* gp = (const float4*)g;
    const float4* bp = (const float4*)b;
    #pragma unroll
    for (int i = 0; i < 4; i++) {
        float4 gg = gp[lane + 32 * i], bb = bp[lane + 32 * i], o;
        o.x = (v[i].x - mean) * rstd * gg.x + bb.x;
        o.y = (v[i].y - mean) * rstd * gg.y + bb.y;
        o.z = (v[i].z - mean) * rstd * gg.z + bb.z;
        o.w = (v[i].w - mean) * rstd * gg.w + bb.w;
        xp[lane + 32 * i] = o;
    }
}

// ---------------------------------------------------------------------------
// LM head (warp per row): logits[row, v] = x[row,:] @ W_lm[:, v] + b_lm[v]
// ---------------------------------------------------------------------------
__global__ void lmhead_kernel(const float* __restrict__ x, const float* __restrict__ Wlm,
                              const float* __restrict__ blm, float* __restrict__ logits) {
    int warp = threadIdx.x >> 5;
    int lane = threadIdx.x & 31;
    size_t row = (size_t)blockIdx.x * 8 + warp;

    float p[VV];
    #pragma unroll
    for (int vv = 0; vv < VV; vv++) p[vv] = 0.f;

    const float* xr = x + row * CC;
    for (int kk = lane; kk < CC; kk += 32) {
        float xv = xr[kk];
        const float* wrow = Wlm + (size_t)kk * VV;
        #pragma unroll
        for (int vv = 0; vv < VV; vv++) p[vv] += xv * wrow[vv];
    }
    #pragma unroll
    for (int vv = 0; vv < VV; vv++)
        #pragma unroll
        for (int o = 16; o; o >>= 1) p[vv] += __shfl_xor_sync(0xffffffffu, p[vv], o);

    if (lane == 0) {
        float* lp = logits + row * VV;
        #pragma unroll
        for (int vv = 0; vv < VV; vv++) lp[vv] = p[vv] + blm[vv];
    }
}

// ---------------------------------------------------------------------------
// Loss: -mean_b log_softmax(logits[b, T-1, :])[label[b]]
// ---------------------------------------------------------------------------
__global__ void loss_kernel(const float* __restrict__ logits, const int* __restrict__ label,
                            float* __restrict__ out_loss) {
    __shared__ float sdata[512];
    int b = threadIdx.x;                   // 512 threads
    const float* lg = logits + ((size_t)b * TT + (TT - 1)) * VV;
    float m = lg[0];
    #pragma unroll
    for (int vv = 1; vv < VV; vv++) m = fmaxf(m, lg[vv]);
    float s = 0.f;
    #pragma unroll
    for (int vv = 0; vv < VV; vv++) s += expf(lg[vv] - m);
    float lse = m + logf(s);
    sdata[b] = -(lg[label[b]] - lse);
    __syncthreads();
    for (int st = 256; st; st >>= 1) {
        if (b < st) sdata[b] += sdata[b + st];
        __syncthreads();
    }
    if (b == 0) *out_loss = sdata[0] * (1.f / BB);
}

// ---------------------------------------------------------------------------
// Host driver
// ---------------------------------------------------------------------------
extern "C" void kernel_launch(void* const* d_in, const int* in_sizes, int n_in,
                              void* d_out, int out_size) {
    const int*   tok   = (const int*)d_in[0];
    const int*   label = (const int*)d_in[1];
    const float* wte   = (const float*)d_in[2];
    const float* wpe   = (const float*)d_in[3];
    const float* Wq    = (const float*)d_in[4];
    const float* bq    = (const float*)d_in[5];
    const float* Wk    = (const float*)d_in[6];
    const float* bk    = (const float*)d_in[7];
    const float* Wv    = (const float*)d_in[8];
    const float* bv    = (const float*)d_in[9];
    const float* Wo    = (const float*)d_in[10];
    const float* bo    = (const float*)d_in[11];
    const float* ln_g  = (const float*)d_in[12];
    const float* ln_b  = (const float*)d_in[13];
    const float* Wlm   = (const float*)d_in[14];
    const float* blm   = (const float*)d_in[15];
    float* out = (float*)d_out;

    float* base = nullptr;
    cudaGetSymbolAddress((void**)&base, g_scratch);
    float* x   = base + 0 * BUF_ELEMS;
    float* q   = base + 1 * BUF_ELEMS;
    float* k   = base + 2 * BUF_ELEMS;
    float* v   = base + 3 * BUF_ELEMS;
    float* hid = base + 4 * BUF_ELEMS;
    float* y   = base + 5 * BUF_ELEMS;

    dim3 gemm_grid(4, MM / 128);

    embed_kernel<<<MM, 128>>>(tok, wte, wpe, x);

    for (int l = 0; l < LL; l++) {
        const size_t wOff = (size_t)l * CC * CC;
        const size_t bOff = (size_t)l * CC;
        sgemm_kernel<<<gemm_grid, 256>>>(x, Wq + wOff, bq + bOff, nullptr, q);
        sgemm_kernel<<<gemm_grid, 256>>>(x, Wk + wOff, bk + bOff, nullptr, k);
        sgemm_kernel<<<gemm_grid, 256>>>(x, Wv + wOff, bv + bOff, nullptr, v);
        attn_kernel<<<MM, 64>>>(q, k, v, hid);
        sgemm_kernel<<<gemm_grid, 256>>>(hid, Wo + wOff, bo + bOff, x, y);
        ln_kernel<<<MM / 8, 256>>>(y, ln_g + bOff, ln_b + bOff, x);
    }

    lmhead_kernel<<<MM / 8, 256>>>(x, Wlm, blm, out);

    if (out_size >= MM * VV + 1)
        loss_kernel<<<1, 512>>>(out, label, out + (MM * VV));
}